// round 15
// baseline (speedup 1.0000x reference)
#include <cuda_runtime.h>
#include <cstdint>

// Problem constants
#define BSZ   2
#define TLEN  2048
#define NEMBD 1024
#define NHEAD 16
#define HS    64
#define MASK_VAL (-10.0f)
#define EMASK   4.5399929762484854e-05f   // exp(-10), exact masked-key weight
#define BT (BSZ * TLEN)       // 4096
#define C3 (3 * NEMBD)        // 3072
#define NBH (BSZ * NHEAD)     // 32
#define NT64 (TLEN / 64)      // 32 key tiles of 64

// Scratch (device globals: no allocations allowed)
__device__ float g_qkv [(size_t)BT * C3];       // tf32-rounded values
__device__ float g_y   [(size_t)BT * NEMBD];    // tf32-rounded values
__device__ float g_vsuf[(size_t)NBH * (NT64 + 1) * HS];

// ---------------------------------------------------------------------------
// helpers
// ---------------------------------------------------------------------------
__device__ __forceinline__ uint32_t f2tf32(float x) {
    uint32_t r;
    asm("cvt.rna.tf32.f32 %0, %1;" : "=r"(r) : "f"(x));
    return r;
}

// rna-round a raw fp32 bit pattern to tf32 (in-register, post-ldmatrix)
__device__ __forceinline__ uint32_t cvtbits(uint32_t b) {
    return f2tf32(__uint_as_float(b));
}

__device__ __forceinline__ void mma8(float* c, const uint32_t* a, const uint32_t* b) {
    asm volatile(
        "mma.sync.aligned.m16n8k8.row.col.f32.tf32.tf32.f32 "
        "{%0,%1,%2,%3}, {%4,%5,%6,%7}, {%8,%9}, {%0,%1,%2,%3};\n"
        : "+f"(c[0]), "+f"(c[1]), "+f"(c[2]), "+f"(c[3])
        : "r"(a[0]), "r"(a[1]), "r"(a[2]), "r"(a[3]),
          "r"(b[0]), "r"(b[1]));
}

__device__ __forceinline__ void ldsm4(uint32_t* r, uint32_t addr) {
    asm volatile("ldmatrix.sync.aligned.m8n8.x4.shared.b16 {%0,%1,%2,%3}, [%4];"
                 : "=r"(r[0]), "=r"(r[1]), "=r"(r[2]), "=r"(r[3]) : "r"(addr));
}

__device__ __forceinline__ void cp16(uint32_t s, const void* g) {
    asm volatile("cp.async.cg.shared.global [%0], [%1], 16;" :: "r"(s), "l"(g));
}

// ---------------------------------------------------------------------------
// GEMM (R8 structure, proven 183us on gemm1): C[M,N] = A[M,K] * B[N,K]^T.
// 128x128 block, BK=16, 3-stage cp.async pipeline (wait_group 1), 256
// threads = 8 warps (2M x 4N), warp tile 64x32, <=128 regs so 2 blocks/SM.
// NEW vs R8: raw fp32 inputs; every fragment is rna-rounded to tf32
// in-register after ldmatrix (identical numerics to the old pre-round pass,
// no extra global traffic). roundC!=0: store tf32-rounded C.
// ---------------------------------------------------------------------------
#define GSW 20
#define GST (128 * GSW)        // words per matrix per stage
__global__ __launch_bounds__(256, 2) void gemm_tf32(
    const float* __restrict__ A, const float* __restrict__ B,
    float* __restrict__ Cmat, int M, int N, int K, int roundC)
{
    extern __shared__ uint32_t gsm[];
    uint32_t* Asm = gsm;               // [3][GST]
    uint32_t* Bsm = gsm + 3 * GST;     // [3][GST]

    const int tid  = threadIdx.x;
    const int lane = tid & 31;
    const int warp = tid >> 5;
    const int wm   = warp >> 2;
    const int wn   = warp & 3;
    const int m0   = blockIdx.y * 128;
    const int n0   = blockIdx.x * 128;

    const int lrow = tid >> 1;
    const int lk8  = (tid & 1) * 8;

    const float* Ap = A + (size_t)(m0 + lrow) * K + lk8;
    const float* Bp = B + (size_t)(n0 + lrow) * K + lk8;

    const int ar = lane & 15;
    const int ac = (lane >> 4) * 4;
    const int br = ((lane >> 4) << 3) + (lane & 7);
    const int bc = ((lane >> 3) & 1) * 4;

    const uint32_t sA = (uint32_t)__cvta_generic_to_shared(Asm);
    const uint32_t sB = (uint32_t)__cvta_generic_to_shared(Bsm);
    const uint32_t ldoff = (uint32_t)(lrow * GSW + lk8) * 4u;

    float acc[4][4][4];
    #pragma unroll
    for (int i = 0; i < 4; ++i)
        #pragma unroll
        for (int j = 0; j < 4; ++j)
            #pragma unroll
            for (int c = 0; c < 4; ++c) acc[i][j][c] = 0.0f;

    const int NKB = K / 16;

    #pragma unroll
    for (int p = 0; p < 2; ++p) {
        uint32_t da = sA + (uint32_t)(p * GST) * 4u + ldoff;
        uint32_t db = sB + (uint32_t)(p * GST) * 4u + ldoff;
        const float* ap = Ap + p * 16;
        const float* bp = Bp + p * 16;
        cp16(da, ap); cp16(da + 16, ap + 4);
        cp16(db, bp); cp16(db + 16, bp + 4);
        asm volatile("cp.async.commit_group;");
    }

    for (int kb = 0; kb < NKB; ++kb) {
        const int st = kb % 3;
        asm volatile("cp.async.wait_group 1;");
        __syncthreads();

        if (kb + 2 < NKB) {
            const int sn = (kb + 2) % 3;
            uint32_t da = sA + (uint32_t)(sn * GST) * 4u + ldoff;
            uint32_t db = sB + (uint32_t)(sn * GST) * 4u + ldoff;
            const float* ap = Ap + (kb + 2) * 16;
            const float* bp = Bp + (kb + 2) * 16;
            cp16(da, ap); cp16(da + 16, ap + 4);
            cp16(db, bp); cp16(db + 16, bp + 4);
        }
        asm volatile("cp.async.commit_group;");

        const uint32_t so = (uint32_t)(st * GST) * 4u;
        #pragma unroll
        for (int ks = 0; ks < 2; ++ks) {
            const int k0 = ks * 8;
            uint32_t af[4][4], bf[4][2];
            #pragma unroll
            for (int i = 0; i < 4; ++i) {
                ldsm4(af[i], sA + so + (uint32_t)((wm * 64 + i * 16 + ar) * GSW + k0 + ac) * 4u);
                af[i][0] = cvtbits(af[i][0]); af[i][1] = cvtbits(af[i][1]);
                af[i][2] = cvtbits(af[i][2]); af[i][3] = cvtbits(af[i][3]);
            }
            #pragma unroll
            for (int jp = 0; jp < 2; ++jp) {
                uint32_t r[4];
                ldsm4(r, sB + so + (uint32_t)((wn * 32 + jp * 16 + br) * GSW + k0 + bc) * 4u);
                bf[2 * jp][0]     = cvtbits(r[0]); bf[2 * jp][1]     = cvtbits(r[1]);
                bf[2 * jp + 1][0] = cvtbits(r[2]); bf[2 * jp + 1][1] = cvtbits(r[3]);
            }
            #pragma unroll
            for (int i = 0; i < 4; ++i)
                #pragma unroll
                for (int j = 0; j < 4; ++j)
                    mma8(acc[i][j], af[i], bf[j]);
        }
    }

    #pragma unroll
    for (int i = 0; i < 4; ++i) {
        const int row0 = m0 + wm * 64 + i * 16 + (lane >> 2);
        #pragma unroll
        for (int j = 0; j < 4; ++j) {
            const int col = n0 + wn * 32 + j * 8 + 2 * (lane & 3);
            float2 v0, v1;
            if (roundC) {
                v0 = make_float2(__uint_as_float(f2tf32(acc[i][j][0])),
                                 __uint_as_float(f2tf32(acc[i][j][1])));
                v1 = make_float2(__uint_as_float(f2tf32(acc[i][j][2])),
                                 __uint_as_float(f2tf32(acc[i][j][3])));
            } else {
                v0 = make_float2(acc[i][j][0], acc[i][j][1]);
                v1 = make_float2(acc[i][j][2], acc[i][j][3]);
            }
            *(float2*)&Cmat[(size_t)row0 * N + col]       = v0;
            *(float2*)&Cmat[(size_t)(row0 + 8) * N + col] = v1;
        }
    }
}

// ---------------------------------------------------------------------------
// V suffix sums at 64-key-tile granularity (soft-mask closed form).
// ---------------------------------------------------------------------------
__global__ void vsuf_partial(const float* __restrict__ qkv) {
    const int t  = blockIdx.x;
    const int bh = blockIdx.y;
    const int b = bh >> 4, h = bh & 15;
    const int d = threadIdx.x;
    float s = 0.0f;
    const float* base = qkv + (size_t)(b * TLEN + t * 64) * C3 + 2 * NEMBD + h * HS + d;
    #pragma unroll 8
    for (int r = 0; r < 64; ++r) s += base[(size_t)r * C3];
    g_vsuf[((size_t)bh * (NT64 + 1) + t) * HS + d] = s;
}

__global__ void vsuf_suffix() {
    const int bh = blockIdx.x;
    const int d  = threadIdx.x;
    float* p = g_vsuf + (size_t)bh * (NT64 + 1) * HS + d;
    p[(size_t)NT64 * HS] = 0.0f;
    float run = 0.0f;
    for (int t = NT64 - 1; t >= 0; --t) {
        run += p[(size_t)t * HS];
        p[(size_t)t * HS] = run;
    }
}

// ---------------------------------------------------------------------------
// Attention (exact R8 — proven ~220us): 128 threads = 4 warps x 16 q-rows,
// 64x64 tiles, grid (32 qblk, 32 bh) heavy-first. Fixed-shift softmax
// (masked weight = exp(-10) exactly), suffix-V closed-form tail.
// Scalar-LDS fragments; raw tile copies (qkv is tf32-rounded by gemm1).
// ---------------------------------------------------------------------------
#define ASW 68
__global__ __launch_bounds__(128) void attn_mma(
    const float* __restrict__ qkv, float* __restrict__ y)
{
    extern __shared__ float sm[];
    float* Qs = sm;                  // [64][68]  (Q * 0.125, already tf32)
    float* Ks = Qs + 64 * ASW;       // [64 keys][68 d]  (also vsuf stage)
    float* Vs = Ks + 64 * ASW;       // [64 keys][68 d]
    float* Ps = Vs + 64 * ASW;       // [64 q][68 keys]  (tf32 weights)

    const int tid  = threadIdx.x;
    const int lane = tid & 31;
    const int w    = tid >> 5;
    const int bh   = blockIdx.y;
    const int b = bh >> 4, h = bh & 15;
    const int qblk = gridDim.x - 1 - blockIdx.x;   // heavy first
    const int q0   = qblk * 64;

    const int qr = lane >> 2;
    const int c4 = lane & 3;

    const uint32_t* Qu = (const uint32_t*)Qs;
    const uint32_t* Ku = (const uint32_t*)Ks;
    const uint32_t* Vu = (const uint32_t*)Vs;
    const uint32_t* Pu = (const uint32_t*)Ps;
    uint32_t* Psu = (uint32_t*)Ps;

    // Load Q tile (scale 1/sqrt(64) = 0.125: exact on tf32 values)
    for (int idx = tid; idx < 64 * 16; idx += 128) {
        const int r = idx >> 4, dq = (idx & 15) * 4;
        float4 v = *(const float4*)(qkv + (size_t)(b * TLEN + q0 + r) * C3 + h * HS + dq);
        *(float4*)&Qs[r * ASW + dq] =
            make_float4(v.x * 0.125f, v.y * 0.125f, v.z * 0.125f, v.w * 0.125f);
    }

    float oacc[8][4];
    #pragma unroll
    for (int j = 0; j < 8; ++j)
        #pragma unroll
        for (int c = 0; c < 4; ++c) oacc[j][c] = 0.0f;
    float lA = 0.0f, lB = 0.0f;

    __syncthreads();

    for (int kt = 0; kt <= qblk; ++kt) {
        // K and V tiles: raw copies (already tf32)
        for (int idx = tid; idx < 64 * 16; idx += 128) {
            const int r = idx >> 4, dq = (idx & 15) * 4;
            const float* base = qkv + (size_t)(b * TLEN + kt * 64 + r) * C3 + h * HS;
            *(float4*)&Ks[r * ASW + dq] = *(const float4*)(base + NEMBD + dq);
            *(float4*)&Vs[r * ASW + dq] = *(const float4*)(base + 2 * NEMBD + dq);
        }
        __syncthreads();

        // S = Q K^T : warp rows w*16..w*16+15 x 64 keys
        float sacc[8][4];
        #pragma unroll
        for (int j = 0; j < 8; ++j)
            #pragma unroll
            for (int c = 0; c < 4; ++c) sacc[j][c] = 0.0f;

        #pragma unroll
        for (int ks = 0; ks < 8; ++ks) {
            const int k0 = ks * 8;
            uint32_t af[4];
            const int mb = w * 16 + qr;
            af[0] = Qu[mb * ASW + k0 + c4];
            af[1] = Qu[(mb + 8) * ASW + k0 + c4];
            af[2] = Qu[mb * ASW + k0 + 4 + c4];
            af[3] = Qu[(mb + 8) * ASW + k0 + 4 + c4];
            #pragma unroll
            for (int j = 0; j < 8; ++j) {
                uint32_t bf[2];
                bf[0] = Ku[(j * 8 + qr) * ASW + k0 + c4];
                bf[1] = Ku[(j * 8 + qr) * ASW + k0 + 4 + c4];
                mma8(sacc[j], af, bf);
            }
        }

        // Fixed-shift softmax weights + P store (tf32)
        const bool domask = (kt == qblk);
        const int rl  = w * 16 + qr;
        const int rgA = q0 + rl, rgB = rgA + 8;
        #pragma unroll
        for (int j = 0; j < 8; ++j) {
            float p0 = __expf(sacc[j][0]);
            float p1 = __expf(sacc[j][1]);
            float p2 = __expf(sacc[j][2]);
            float p3 = __expf(sacc[j][3]);
            if (domask) {
                const int kg = kt * 64 + j * 8 + 2 * c4;
                if (kg     > rgA) p0 = EMASK;
                if (kg + 1 > rgA) p1 = EMASK;
                if (kg     > rgB) p2 = EMASK;
                if (kg + 1 > rgB) p3 = EMASK;
            }
            lA += p0 + p1;
            lB += p2 + p3;
            *(uint2*)&Psu[rl * ASW + j * 8 + 2 * c4] =
                make_uint2(f2tf32(p0), f2tf32(p1));
            *(uint2*)&Psu[(rl + 8) * ASW + j * 8 + 2 * c4] =
                make_uint2(f2tf32(p2), f2tf32(p3));
        }
        __syncwarp();   // P rows are warp-private

        // O += P V
        #pragma unroll
        for (int ks = 0; ks < 8; ++ks) {
            const int k0 = ks * 8;
            uint32_t af[4];
            const int mb = w * 16 + qr;
            af[0] = Pu[mb * ASW + k0 + c4];
            af[1] = Pu[(mb + 8) * ASW + k0 + c4];
            af[2] = Pu[mb * ASW + k0 + 4 + c4];
            af[3] = Pu[(mb + 8) * ASW + k0 + 4 + c4];
            #pragma unroll
            for (int j = 0; j < 8; ++j) {
                uint32_t bf[2];
                bf[0] = Vu[(k0 + c4) * ASW + j * 8 + qr];
                bf[1] = Vu[(k0 + 4 + c4) * ASW + j * 8 + qr];
                mma8(oacc[j], af, bf);
            }
        }
        __syncthreads();   // protect Ks/Vs before next tile load
    }

    // Tail: strictly-future keys, uniform weight EMASK * suffix V sum
    const int nmask = TLEN - 64 * (qblk + 1);
    for (int d = tid; d < HS; d += 128)
        Ks[d] = g_vsuf[((size_t)bh * (NT64 + 1) + qblk + 1) * HS + d];
    __syncthreads();

    lA += __shfl_xor_sync(0xffffffffu, lA, 1);
    lA += __shfl_xor_sync(0xffffffffu, lA, 2);
    lB += __shfl_xor_sync(0xffffffffu, lB, 1);
    lB += __shfl_xor_sync(0xffffffffu, lB, 2);
    const float invA = 1.0f / (lA + (float)nmask * EMASK);
    const float invB = 1.0f / (lB + (float)nmask * EMASK);

    const int rowA = b * TLEN + q0 + w * 16 + qr;
    float* yA = y + (size_t)rowA * NEMBD + h * HS;
    float* yB = y + (size_t)(rowA + 8) * NEMBD + h * HS;
    #pragma unroll
    for (int j = 0; j < 8; ++j) {
        const int d0 = j * 8 + 2 * c4;
        const float v0 = Ks[d0], v1 = Ks[d0 + 1];
        // y is consumed by the proj MMA: emit tf32-rounded values
        *(uint2*)&yA[d0] = make_uint2(f2tf32((oacc[j][0] + EMASK * v0) * invA),
                                      f2tf32((oacc[j][1] + EMASK * v1) * invA));
        *(uint2*)&yB[d0] = make_uint2(f2tf32((oacc[j][2] + EMASK * v0) * invB),
                                      f2tf32((oacc[j][3] + EMASK * v1) * invB));
    }
}

// ---------------------------------------------------------------------------
extern "C" void kernel_launch(void* const* d_in, const int* in_sizes, int n_in,
                              void* d_out, int out_size)
{
    const float* x      = (const float*)d_in[0];
    const float* w_attn = (const float*)d_in[1];
    const float* w_proj = (const float*)d_in[2];
    float* out = (float*)d_out;

    float *qkv, *y;
    cudaGetSymbolAddress((void**)&qkv, g_qkv);
    cudaGetSymbolAddress((void**)&y,   g_y);

    const int gemm_smem = 6 * GST * (int)sizeof(uint32_t);   // 61440 B
    const int attn_smem = 4 * 64 * ASW * (int)sizeof(float); // 69632 B
    cudaFuncSetAttribute(gemm_tf32, cudaFuncAttributeMaxDynamicSharedMemorySize, gemm_smem);
    cudaFuncSetAttribute(attn_mma,  cudaFuncAttributeMaxDynamicSharedMemorySize, attn_smem);

    // 1) QKV projection straight from raw inputs (fragments rna-rounded
    //    in-register; output tf32-rounded for the attention MMAs)
    gemm_tf32<<<dim3(C3 / 128, BT / 128), 256, gemm_smem>>>(
        x, w_attn, qkv, BT, C3, NEMBD, 1);

    // 2) V suffix sums
    vsuf_partial<<<dim3(NT64, NBH), 64>>>(qkv);
    vsuf_suffix<<<NBH, 64>>>();

    // 3) Attention (causal part + closed-form masked tail)
    attn_mma<<<dim3(NT64, NBH), 128, attn_smem>>>(qkv, y);

    // 4) Output projection (final output: full fp32)
    gemm_tf32<<<dim3(NEMBD / 128, BT / 128), 256, gemm_smem>>>(
        y, w_proj, out, BT, NEMBD, NEMBD, 0);
}

// round 16
// speedup vs baseline: 1.0890x; 1.0890x over previous
#include <cuda_runtime.h>
#include <cstdint>

// Problem constants
#define BSZ   2
#define TLEN  2048
#define NEMBD 1024
#define NHEAD 16
#define HS    64
#define MASK_VAL (-10.0f)
#define EMASK   4.5399929762484854e-05f   // exp(-10), exact masked-key weight
#define BT (BSZ * TLEN)       // 4096
#define C3 (3 * NEMBD)        // 3072
#define NBH (BSZ * NHEAD)     // 32
#define NT64 (TLEN / 64)      // 32 key tiles of 64

// Scratch (device globals: no allocations allowed)
__device__ float g_qkv [(size_t)BT * C3];       // tf32-rounded values
__device__ float g_y   [(size_t)BT * NEMBD];    // tf32-rounded values
__device__ float g_vsuf[(size_t)NBH * NT64 * HS];   // per-tile V partial sums
__device__ float g_xc  [(size_t)BT * NEMBD];    // tf32-rounded x
__device__ float g_wac [(size_t)C3 * NEMBD];    // tf32-rounded w_attn
__device__ float g_wpc [(size_t)NEMBD * NEMBD]; // tf32-rounded w_proj

// ---------------------------------------------------------------------------
// helpers
// ---------------------------------------------------------------------------
__device__ __forceinline__ uint32_t f2tf32(float x) {
    uint32_t r;
    asm("cvt.rna.tf32.f32 %0, %1;" : "=r"(r) : "f"(x));
    return r;
}

__device__ __forceinline__ void mma8(float* c, const uint32_t* a, const uint32_t* b) {
    asm volatile(
        "mma.sync.aligned.m16n8k8.row.col.f32.tf32.tf32.f32 "
        "{%0,%1,%2,%3}, {%4,%5,%6,%7}, {%8,%9}, {%0,%1,%2,%3};\n"
        : "+f"(c[0]), "+f"(c[1]), "+f"(c[2]), "+f"(c[3])
        : "r"(a[0]), "r"(a[1]), "r"(a[2]), "r"(a[3]),
          "r"(b[0]), "r"(b[1]));
}

__device__ __forceinline__ void ldsm4(uint32_t* r, uint32_t addr) {
    asm volatile("ldmatrix.sync.aligned.m8n8.x4.shared.b16 {%0,%1,%2,%3}, [%4];"
                 : "=r"(r[0]), "=r"(r[1]), "=r"(r[2]), "=r"(r[3]) : "r"(addr));
}

__device__ __forceinline__ void cp16(uint32_t s, const void* g) {
    asm volatile("cp.async.cg.shared.global [%0], [%1], 16;" :: "r"(s), "l"(g));
}

// ---------------------------------------------------------------------------
// tf32 pre-round, all three inputs in one launch (3 segments)
// ---------------------------------------------------------------------------
__global__ void round_all(const float* __restrict__ x,
                          const float* __restrict__ wa,
                          const float* __restrict__ wp)
{
    const int n1 = BT * NEMBD / 4;        // x
    const int n2 = C3 * NEMBD / 4;        // w_attn
    const int n3 = NEMBD * NEMBD / 4;     // w_proj
    const int ntot = n1 + n2 + n3;
    for (int i = blockIdx.x * blockDim.x + threadIdx.x; i < ntot;
         i += gridDim.x * blockDim.x) {
        const float4* src;
        uint4* dst;
        int k;
        if (i < n1)           { src = (const float4*)x,  dst = (uint4*)g_xc,  k = i; }
        else if (i < n1 + n2) { src = (const float4*)wa, dst = (uint4*)g_wac, k = i - n1; }
        else                  { src = (const float4*)wp, dst = (uint4*)g_wpc, k = i - n1 - n2; }
        float4 v = src[k];
        dst[k] = make_uint4(f2tf32(v.x), f2tf32(v.y), f2tf32(v.z), f2tf32(v.w));
    }
}

// ---------------------------------------------------------------------------
// GEMM (exact R9 config — measured 183us on gemm1): C[M,N] = A[M,K]*B[N,K]^T,
// tf32 mma.sync. 128x128 block, BK=16, 3-stage cp.async pipeline
// (wait_group 1), 256 threads = 8 warps (2M x 4N), warp tile 64x32,
// <=128 regs so 2 blocks/SM. Inputs PRE-ROUNDED tf32 (no cvt in mainloop).
// roundC!=0: store tf32-rounded C.
// ---------------------------------------------------------------------------
#define GSW 20
#define GST (128 * GSW)        // words per matrix per stage
__global__ __launch_bounds__(256, 2) void gemm_tf32(
    const float* __restrict__ A, const float* __restrict__ B,
    float* __restrict__ Cmat, int M, int N, int K, int roundC)
{
    extern __shared__ uint32_t gsm[];
    uint32_t* Asm = gsm;               // [3][GST]
    uint32_t* Bsm = gsm + 3 * GST;     // [3][GST]

    const int tid  = threadIdx.x;
    const int lane = tid & 31;
    const int warp = tid >> 5;
    const int wm   = warp >> 2;
    const int wn   = warp & 3;
    const int m0   = blockIdx.y * 128;
    const int n0   = blockIdx.x * 128;

    const int lrow = tid >> 1;
    const int lk8  = (tid & 1) * 8;

    const float* Ap = A + (size_t)(m0 + lrow) * K + lk8;
    const float* Bp = B + (size_t)(n0 + lrow) * K + lk8;

    const int ar = lane & 15;
    const int ac = (lane >> 4) * 4;
    const int br = ((lane >> 4) << 3) + (lane & 7);
    const int bc = ((lane >> 3) & 1) * 4;

    const uint32_t sA = (uint32_t)__cvta_generic_to_shared(Asm);
    const uint32_t sB = (uint32_t)__cvta_generic_to_shared(Bsm);
    const uint32_t ldoff = (uint32_t)(lrow * GSW + lk8) * 4u;

    float acc[4][4][4];
    #pragma unroll
    for (int i = 0; i < 4; ++i)
        #pragma unroll
        for (int j = 0; j < 4; ++j)
            #pragma unroll
            for (int c = 0; c < 4; ++c) acc[i][j][c] = 0.0f;

    const int NKB = K / 16;

    #pragma unroll
    for (int p = 0; p < 2; ++p) {
        uint32_t da = sA + (uint32_t)(p * GST) * 4u + ldoff;
        uint32_t db = sB + (uint32_t)(p * GST) * 4u + ldoff;
        const float* ap = Ap + p * 16;
        const float* bp = Bp + p * 16;
        cp16(da, ap); cp16(da + 16, ap + 4);
        cp16(db, bp); cp16(db + 16, bp + 4);
        asm volatile("cp.async.commit_group;");
    }

    for (int kb = 0; kb < NKB; ++kb) {
        const int st = kb % 3;
        asm volatile("cp.async.wait_group 1;");
        __syncthreads();

        if (kb + 2 < NKB) {
            const int sn = (kb + 2) % 3;
            uint32_t da = sA + (uint32_t)(sn * GST) * 4u + ldoff;
            uint32_t db = sB + (uint32_t)(sn * GST) * 4u + ldoff;
            const float* ap = Ap + (kb + 2) * 16;
            const float* bp = Bp + (kb + 2) * 16;
            cp16(da, ap); cp16(da + 16, ap + 4);
            cp16(db, bp); cp16(db + 16, bp + 4);
        }
        asm volatile("cp.async.commit_group;");

        const uint32_t so = (uint32_t)(st * GST) * 4u;
        #pragma unroll
        for (int ks = 0; ks < 2; ++ks) {
            const int k0 = ks * 8;
            uint32_t af[4][4], bf[4][2];
            #pragma unroll
            for (int i = 0; i < 4; ++i)
                ldsm4(af[i], sA + so + (uint32_t)((wm * 64 + i * 16 + ar) * GSW + k0 + ac) * 4u);
            #pragma unroll
            for (int jp = 0; jp < 2; ++jp) {
                uint32_t r[4];
                ldsm4(r, sB + so + (uint32_t)((wn * 32 + jp * 16 + br) * GSW + k0 + bc) * 4u);
                bf[2 * jp][0] = r[0]; bf[2 * jp][1] = r[1];
                bf[2 * jp + 1][0] = r[2]; bf[2 * jp + 1][1] = r[3];
            }
            #pragma unroll
            for (int i = 0; i < 4; ++i)
                #pragma unroll
                for (int j = 0; j < 4; ++j)
                    mma8(acc[i][j], af[i], bf[j]);
        }
    }

    #pragma unroll
    for (int i = 0; i < 4; ++i) {
        const int row0 = m0 + wm * 64 + i * 16 + (lane >> 2);
        #pragma unroll
        for (int j = 0; j < 4; ++j) {
            const int col = n0 + wn * 32 + j * 8 + 2 * (lane & 3);
            float2 v0, v1;
            if (roundC) {
                v0 = make_float2(__uint_as_float(f2tf32(acc[i][j][0])),
                                 __uint_as_float(f2tf32(acc[i][j][1])));
                v1 = make_float2(__uint_as_float(f2tf32(acc[i][j][2])),
                                 __uint_as_float(f2tf32(acc[i][j][3])));
            } else {
                v0 = make_float2(acc[i][j][0], acc[i][j][1]);
                v1 = make_float2(acc[i][j][2], acc[i][j][3]);
            }
            *(float2*)&Cmat[(size_t)row0 * N + col]       = v0;
            *(float2*)&Cmat[(size_t)(row0 + 8) * N + col] = v1;
        }
    }
}

// ---------------------------------------------------------------------------
// V partial sums per 64-key tile (suffix summed inside the attention tail).
// ---------------------------------------------------------------------------
__global__ void vsuf_partial(const float* __restrict__ qkv) {
    const int t  = blockIdx.x;
    const int bh = blockIdx.y;
    const int b = bh >> 4, h = bh & 15;
    const int d = threadIdx.x;
    float s = 0.0f;
    const float* base = qkv + (size_t)(b * TLEN + t * 64) * C3 + 2 * NEMBD + h * HS + d;
    #pragma unroll 8
    for (int r = 0; r < 64; ++r) s += base[(size_t)r * C3];
    g_vsuf[((size_t)bh * NT64 + t) * HS + d] = s;
}

// ---------------------------------------------------------------------------
// Attention (exact R8/R9 hot loop — proven ~220us): 128 threads = 4 warps x
// 16 q-rows, 64x64 tiles, grid (32 qblk, 32 bh) heavy-first. Fixed-shift
// softmax (masked weight = exp(-10) exactly). Tail sums the per-tile V
// partials for t > qblk in-kernel (vsuf_suffix launch deleted).
// ---------------------------------------------------------------------------
#define ASW 68
__global__ __launch_bounds__(128) void attn_mma(
    const float* __restrict__ qkv, float* __restrict__ y)
{
    extern __shared__ float sm[];
    float* Qs = sm;                  // [64][68]  (Q * 0.125, already tf32)
    float* Ks = Qs + 64 * ASW;       // [64 keys][68 d]  (also vsuf stage)
    float* Vs = Ks + 64 * ASW;       // [64 keys][68 d]
    float* Ps = Vs + 64 * ASW;       // [64 q][68 keys]  (tf32 weights)

    const int tid  = threadIdx.x;
    const int lane = tid & 31;
    const int w    = tid >> 5;
    const int bh   = blockIdx.y;
    const int b = bh >> 4, h = bh & 15;
    const int qblk = gridDim.x - 1 - blockIdx.x;   // heavy first
    const int q0   = qblk * 64;

    const int qr = lane >> 2;
    const int c4 = lane & 3;

    const uint32_t* Qu = (const uint32_t*)Qs;
    const uint32_t* Ku = (const uint32_t*)Ks;
    const uint32_t* Vu = (const uint32_t*)Vs;
    const uint32_t* Pu = (const uint32_t*)Ps;
    uint32_t* Psu = (uint32_t*)Ps;

    // Load Q tile (scale 1/sqrt(64) = 0.125: exact on tf32 values)
    for (int idx = tid; idx < 64 * 16; idx += 128) {
        const int r = idx >> 4, dq = (idx & 15) * 4;
        float4 v = *(const float4*)(qkv + (size_t)(b * TLEN + q0 + r) * C3 + h * HS + dq);
        *(float4*)&Qs[r * ASW + dq] =
            make_float4(v.x * 0.125f, v.y * 0.125f, v.z * 0.125f, v.w * 0.125f);
    }

    float oacc[8][4];
    #pragma unroll
    for (int j = 0; j < 8; ++j)
        #pragma unroll
        for (int c = 0; c < 4; ++c) oacc[j][c] = 0.0f;
    float lA = 0.0f, lB = 0.0f;

    __syncthreads();

    for (int kt = 0; kt <= qblk; ++kt) {
        // K and V tiles: raw copies (already tf32)
        for (int idx = tid; idx < 64 * 16; idx += 128) {
            const int r = idx >> 4, dq = (idx & 15) * 4;
            const float* base = qkv + (size_t)(b * TLEN + kt * 64 + r) * C3 + h * HS;
            *(float4*)&Ks[r * ASW + dq] = *(const float4*)(base + NEMBD + dq);
            *(float4*)&Vs[r * ASW + dq] = *(const float4*)(base + 2 * NEMBD + dq);
        }
        __syncthreads();

        // S = Q K^T : warp rows w*16..w*16+15 x 64 keys
        float sacc[8][4];
        #pragma unroll
        for (int j = 0; j < 8; ++j)
            #pragma unroll
            for (int c = 0; c < 4; ++c) sacc[j][c] = 0.0f;

        #pragma unroll
        for (int ks = 0; ks < 8; ++ks) {
            const int k0 = ks * 8;
            uint32_t af[4];
            const int mb = w * 16 + qr;
            af[0] = Qu[mb * ASW + k0 + c4];
            af[1] = Qu[(mb + 8) * ASW + k0 + c4];
            af[2] = Qu[mb * ASW + k0 + 4 + c4];
            af[3] = Qu[(mb + 8) * ASW + k0 + 4 + c4];
            #pragma unroll
            for (int j = 0; j < 8; ++j) {
                uint32_t bf[2];
                bf[0] = Ku[(j * 8 + qr) * ASW + k0 + c4];
                bf[1] = Ku[(j * 8 + qr) * ASW + k0 + 4 + c4];
                mma8(sacc[j], af, bf);
            }
        }

        // Fixed-shift softmax weights + P store (tf32)
        const bool domask = (kt == qblk);
        const int rl  = w * 16 + qr;
        const int rgA = q0 + rl, rgB = rgA + 8;
        #pragma unroll
        for (int j = 0; j < 8; ++j) {
            float p0 = __expf(sacc[j][0]);
            float p1 = __expf(sacc[j][1]);
            float p2 = __expf(sacc[j][2]);
            float p3 = __expf(sacc[j][3]);
            if (domask) {
                const int kg = kt * 64 + j * 8 + 2 * c4;
                if (kg     > rgA) p0 = EMASK;
                if (kg + 1 > rgA) p1 = EMASK;
                if (kg     > rgB) p2 = EMASK;
                if (kg + 1 > rgB) p3 = EMASK;
            }
            lA += p0 + p1;
            lB += p2 + p3;
            *(uint2*)&Psu[rl * ASW + j * 8 + 2 * c4] =
                make_uint2(f2tf32(p0), f2tf32(p1));
            *(uint2*)&Psu[(rl + 8) * ASW + j * 8 + 2 * c4] =
                make_uint2(f2tf32(p2), f2tf32(p3));
        }
        __syncwarp();   // P rows are warp-private

        // O += P V
        #pragma unroll
        for (int ks = 0; ks < 8; ++ks) {
            const int k0 = ks * 8;
            uint32_t af[4];
            const int mb = w * 16 + qr;
            af[0] = Pu[mb * ASW + k0 + c4];
            af[1] = Pu[(mb + 8) * ASW + k0 + c4];
            af[2] = Pu[mb * ASW + k0 + 4 + c4];
            af[3] = Pu[(mb + 8) * ASW + k0 + 4 + c4];
            #pragma unroll
            for (int j = 0; j < 8; ++j) {
                uint32_t bf[2];
                bf[0] = Vu[(k0 + c4) * ASW + j * 8 + qr];
                bf[1] = Vu[(k0 + 4 + c4) * ASW + j * 8 + qr];
                mma8(oacc[j], af, bf);
            }
        }
        __syncthreads();   // protect Ks/Vs before next tile load
    }

    // Tail: strictly-future keys, uniform weight EMASK.
    // Suffix V sum computed here from per-tile partials (t > qblk).
    const int nmask = TLEN - 64 * (qblk + 1);
    for (int d = tid; d < HS; d += 128) {
        float s = 0.0f;
        for (int t = qblk + 1; t < NT64; ++t)
            s += g_vsuf[((size_t)bh * NT64 + t) * HS + d];
        Ks[d] = s;
    }
    __syncthreads();

    lA += __shfl_xor_sync(0xffffffffu, lA, 1);
    lA += __shfl_xor_sync(0xffffffffu, lA, 2);
    lB += __shfl_xor_sync(0xffffffffu, lB, 1);
    lB += __shfl_xor_sync(0xffffffffu, lB, 2);
    const float invA = 1.0f / (lA + (float)nmask * EMASK);
    const float invB = 1.0f / (lB + (float)nmask * EMASK);

    const int rowA = b * TLEN + q0 + w * 16 + qr;
    float* yA = y + (size_t)rowA * NEMBD + h * HS;
    float* yB = y + (size_t)(rowA + 8) * NEMBD + h * HS;
    #pragma unroll
    for (int j = 0; j < 8; ++j) {
        const int d0 = j * 8 + 2 * c4;
        const float v0 = Ks[d0], v1 = Ks[d0 + 1];
        // y is consumed by the proj MMA: emit tf32-rounded values
        *(uint2*)&yA[d0] = make_uint2(f2tf32((oacc[j][0] + EMASK * v0) * invA),
                                      f2tf32((oacc[j][1] + EMASK * v1) * invA));
        *(uint2*)&yB[d0] = make_uint2(f2tf32((oacc[j][2] + EMASK * v0) * invB),
                                      f2tf32((oacc[j][3] + EMASK * v1) * invB));
    }
}

// ---------------------------------------------------------------------------
extern "C" void kernel_launch(void* const* d_in, const int* in_sizes, int n_in,
                              void* d_out, int out_size)
{
    const float* x      = (const float*)d_in[0];
    const float* w_attn = (const float*)d_in[1];
    const float* w_proj = (const float*)d_in[2];
    float* out = (float*)d_out;

    float *qkv, *y, *xc, *wac, *wpc;
    cudaGetSymbolAddress((void**)&qkv, g_qkv);
    cudaGetSymbolAddress((void**)&y,   g_y);
    cudaGetSymbolAddress((void**)&xc,  g_xc);
    cudaGetSymbolAddress((void**)&wac, g_wac);
    cudaGetSymbolAddress((void**)&wpc, g_wpc);

    const int gemm_smem = 6 * GST * (int)sizeof(uint32_t);   // 61440 B
    const int attn_smem = 4 * 64 * ASW * (int)sizeof(float); // 69632 B
    cudaFuncSetAttribute(gemm_tf32, cudaFuncAttributeMaxDynamicSharedMemorySize, gemm_smem);
    cudaFuncSetAttribute(attn_mma,  cudaFuncAttributeMaxDynamicSharedMemorySize, attn_smem);

    // 0) pre-round inputs to tf32, single fused launch
    round_all<<<2048, 256>>>(x, w_attn, w_proj);

    // 1) QKV projection (output tf32-rounded for attention MMAs)
    gemm_tf32<<<dim3(C3 / 128, BT / 128), 256, gemm_smem>>>(
        xc, wac, qkv, BT, C3, NEMBD, 1);

    // 2) V per-tile partial sums (suffix folded into attention tail)
    vsuf_partial<<<dim3(NT64, NBH), 64>>>(qkv);

    // 3) Attention (causal part + closed-form masked tail)
    attn_mma<<<dim3(NT64, NBH), 128, attn_smem>>>(qkv, y);

    // 4) Output projection (final output: full fp32)
    gemm_tf32<<<dim3(NEMBD / 128, BT / 128), 256, gemm_smem>>>(
        y, wpc, out, BT, NEMBD, NEMBD, 0);
}

// round 17
// speedup vs baseline: 1.1081x; 1.0176x over previous
#include <cuda_runtime.h>
#include <cstdint>

// Problem constants
#define BSZ   2
#define TLEN  2048
#define NEMBD 1024
#define NHEAD 16
#define HS    64
#define MASK_VAL (-10.0f)
#define EMASK   4.5399929762484854e-05f   // exp(-10), exact masked-key weight
#define BT (BSZ * TLEN)       // 4096
#define C3 (3 * NEMBD)        // 3072
#define NBH (BSZ * NHEAD)     // 32
#define NT64 (TLEN / 64)      // 32 key tiles of 64

// Scratch (device globals: no allocations allowed)
__device__ float g_qkv [(size_t)BT * C3];       // tf32-rounded values
__device__ float g_y   [(size_t)BT * NEMBD];    // tf32-rounded values
__device__ float g_vsuf[(size_t)NBH * NT64 * HS];   // per-tile V partial sums
__device__ float g_xc  [(size_t)BT * NEMBD];    // tf32-rounded x
__device__ float g_wac [(size_t)C3 * NEMBD];    // tf32-rounded w_attn
__device__ float g_wpc [(size_t)NEMBD * NEMBD]; // tf32-rounded w_proj

// ---------------------------------------------------------------------------
// helpers
// ---------------------------------------------------------------------------
__device__ __forceinline__ uint32_t f2tf32(float x) {
    uint32_t r;
    asm("cvt.rna.tf32.f32 %0, %1;" : "=r"(r) : "f"(x));
    return r;
}

__device__ __forceinline__ void mma8(float* c, const uint32_t* a, const uint32_t* b) {
    asm volatile(
        "mma.sync.aligned.m16n8k8.row.col.f32.tf32.tf32.f32 "
        "{%0,%1,%2,%3}, {%4,%5,%6,%7}, {%8,%9}, {%0,%1,%2,%3};\n"
        : "+f"(c[0]), "+f"(c[1]), "+f"(c[2]), "+f"(c[3])
        : "r"(a[0]), "r"(a[1]), "r"(a[2]), "r"(a[3]),
          "r"(b[0]), "r"(b[1]));
}

__device__ __forceinline__ void ldsm4(uint32_t* r, uint32_t addr) {
    asm volatile("ldmatrix.sync.aligned.m8n8.x4.shared.b16 {%0,%1,%2,%3}, [%4];"
                 : "=r"(r[0]), "=r"(r[1]), "=r"(r[2]), "=r"(r[3]) : "r"(addr));
}

__device__ __forceinline__ void cp16(uint32_t s, const void* g) {
    asm volatile("cp.async.cg.shared.global [%0], [%1], 16;" :: "r"(s), "l"(g));
}

// ---------------------------------------------------------------------------
// tf32 pre-round, all three inputs in one launch (3 segments)
// ---------------------------------------------------------------------------
__global__ void round_all(const float* __restrict__ x,
                          const float* __restrict__ wa,
                          const float* __restrict__ wp)
{
    const int n1 = BT * NEMBD / 4;        // x
    const int n2 = C3 * NEMBD / 4;        // w_attn
    const int n3 = NEMBD * NEMBD / 4;     // w_proj
    const int ntot = n1 + n2 + n3;
    for (int i = blockIdx.x * blockDim.x + threadIdx.x; i < ntot;
         i += gridDim.x * blockDim.x) {
        const float4* src;
        uint4* dst;
        int k;
        if (i < n1)           { src = (const float4*)x,  dst = (uint4*)g_xc,  k = i; }
        else if (i < n1 + n2) { src = (const float4*)wa, dst = (uint4*)g_wac, k = i - n1; }
        else                  { src = (const float4*)wp, dst = (uint4*)g_wpc, k = i - n1 - n2; }
        float4 v = src[k];
        dst[k] = make_uint4(f2tf32(v.x), f2tf32(v.y), f2tf32(v.z), f2tf32(v.w));
    }
}

// ---------------------------------------------------------------------------
// GEMM (exact R9 config — measured 183us on gemm1): C[M,N] = A[M,K]*B[N,K]^T,
// tf32 mma.sync. 128x128 block, BK=16, 3-stage cp.async pipeline
// (wait_group 1), 256 threads = 8 warps (2M x 4N), warp tile 64x32,
// <=128 regs so 2 blocks/SM. Inputs PRE-ROUNDED tf32.
// roundC!=0: store tf32-rounded C.
// ---------------------------------------------------------------------------
#define GSW 20
#define GST (128 * GSW)        // words per matrix per stage
__global__ __launch_bounds__(256, 2) void gemm_tf32(
    const float* __restrict__ A, const float* __restrict__ B,
    float* __restrict__ Cmat, int M, int N, int K, int roundC)
{
    extern __shared__ uint32_t gsm[];
    uint32_t* Asm = gsm;               // [3][GST]
    uint32_t* Bsm = gsm + 3 * GST;     // [3][GST]

    const int tid  = threadIdx.x;
    const int lane = tid & 31;
    const int warp = tid >> 5;
    const int wm   = warp >> 2;
    const int wn   = warp & 3;
    const int m0   = blockIdx.y * 128;
    const int n0   = blockIdx.x * 128;

    const int lrow = tid >> 1;
    const int lk8  = (tid & 1) * 8;

    const float* Ap = A + (size_t)(m0 + lrow) * K + lk8;
    const float* Bp = B + (size_t)(n0 + lrow) * K + lk8;

    const int ar = lane & 15;
    const int ac = (lane >> 4) * 4;
    const int br = ((lane >> 4) << 3) + (lane & 7);
    const int bc = ((lane >> 3) & 1) * 4;

    const uint32_t sA = (uint32_t)__cvta_generic_to_shared(Asm);
    const uint32_t sB = (uint32_t)__cvta_generic_to_shared(Bsm);
    const uint32_t ldoff = (uint32_t)(lrow * GSW + lk8) * 4u;

    float acc[4][4][4];
    #pragma unroll
    for (int i = 0; i < 4; ++i)
        #pragma unroll
        for (int j = 0; j < 4; ++j)
            #pragma unroll
            for (int c = 0; c < 4; ++c) acc[i][j][c] = 0.0f;

    const int NKB = K / 16;

    #pragma unroll
    for (int p = 0; p < 2; ++p) {
        uint32_t da = sA + (uint32_t)(p * GST) * 4u + ldoff;
        uint32_t db = sB + (uint32_t)(p * GST) * 4u + ldoff;
        const float* ap = Ap + p * 16;
        const float* bp = Bp + p * 16;
        cp16(da, ap); cp16(da + 16, ap + 4);
        cp16(db, bp); cp16(db + 16, bp + 4);
        asm volatile("cp.async.commit_group;");
    }

    for (int kb = 0; kb < NKB; ++kb) {
        const int st = kb % 3;
        asm volatile("cp.async.wait_group 1;");
        __syncthreads();

        if (kb + 2 < NKB) {
            const int sn = (kb + 2) % 3;
            uint32_t da = sA + (uint32_t)(sn * GST) * 4u + ldoff;
            uint32_t db = sB + (uint32_t)(sn * GST) * 4u + ldoff;
            const float* ap = Ap + (kb + 2) * 16;
            const float* bp = Bp + (kb + 2) * 16;
            cp16(da, ap); cp16(da + 16, ap + 4);
            cp16(db, bp); cp16(db + 16, bp + 4);
        }
        asm volatile("cp.async.commit_group;");

        const uint32_t so = (uint32_t)(st * GST) * 4u;
        #pragma unroll
        for (int ks = 0; ks < 2; ++ks) {
            const int k0 = ks * 8;
            uint32_t af[4][4], bf[4][2];
            #pragma unroll
            for (int i = 0; i < 4; ++i)
                ldsm4(af[i], sA + so + (uint32_t)((wm * 64 + i * 16 + ar) * GSW + k0 + ac) * 4u);
            #pragma unroll
            for (int jp = 0; jp < 2; ++jp) {
                uint32_t r[4];
                ldsm4(r, sB + so + (uint32_t)((wn * 32 + jp * 16 + br) * GSW + k0 + bc) * 4u);
                bf[2 * jp][0] = r[0]; bf[2 * jp][1] = r[1];
                bf[2 * jp + 1][0] = r[2]; bf[2 * jp + 1][1] = r[3];
            }
            #pragma unroll
            for (int i = 0; i < 4; ++i)
                #pragma unroll
                for (int j = 0; j < 4; ++j)
                    mma8(acc[i][j], af[i], bf[j]);
        }
    }

    #pragma unroll
    for (int i = 0; i < 4; ++i) {
        const int row0 = m0 + wm * 64 + i * 16 + (lane >> 2);
        #pragma unroll
        for (int j = 0; j < 4; ++j) {
            const int col = n0 + wn * 32 + j * 8 + 2 * (lane & 3);
            float2 v0, v1;
            if (roundC) {
                v0 = make_float2(__uint_as_float(f2tf32(acc[i][j][0])),
                                 __uint_as_float(f2tf32(acc[i][j][1])));
                v1 = make_float2(__uint_as_float(f2tf32(acc[i][j][2])),
                                 __uint_as_float(f2tf32(acc[i][j][3])));
            } else {
                v0 = make_float2(acc[i][j][0], acc[i][j][1]);
                v1 = make_float2(acc[i][j][2], acc[i][j][3]);
            }
            *(float2*)&Cmat[(size_t)row0 * N + col]       = v0;
            *(float2*)&Cmat[(size_t)(row0 + 8) * N + col] = v1;
        }
    }
}

// ---------------------------------------------------------------------------
// V partial sums per 64-key tile (suffix summed inside the attention tail).
// ---------------------------------------------------------------------------
__global__ void vsuf_partial(const float* __restrict__ qkv) {
    const int t  = blockIdx.x;
    const int bh = blockIdx.y;
    const int b = bh >> 4, h = bh & 15;
    const int d = threadIdx.x;
    float s = 0.0f;
    const float* base = qkv + (size_t)(b * TLEN + t * 64) * C3 + 2 * NEMBD + h * HS + d;
    #pragma unroll 8
    for (int r = 0; r < 64; ++r) s += base[(size_t)r * C3];
    g_vsuf[((size_t)bh * NT64 + t) * HS + d] = s;
}

// ---------------------------------------------------------------------------
// Attention: R16 structure with HYBRID fragment loads —
//  - A-frags (Q and P, row-major [q][*]) via ldmatrix.x4
//  - K B-frags (row-major [key][d]) via ldmatrix.x4
//  - V B-frags stay scalar LDS (avoids R11's d-major transpose cost)
// Fixed-shift softmax (masked weight = exp(-10) exactly); in-kernel
// suffix-V tail. Numerics bit-identical to R16.
// ---------------------------------------------------------------------------
#define ASW 68
__global__ __launch_bounds__(128) void attn_mma(
    const float* __restrict__ qkv, float* __restrict__ y)
{
    extern __shared__ float sm[];
    float* Qs = sm;                  // [64][68]  (Q * 0.125, already tf32)
    float* Ks = Qs + 64 * ASW;       // [64 keys][68 d]  (also vsuf stage)
    float* Vs = Ks + 64 * ASW;       // [64 keys][68 d]
    float* Ps = Vs + 64 * ASW;       // [64 q][68 keys]  (tf32 weights)

    const int tid  = threadIdx.x;
    const int lane = tid & 31;
    const int w    = tid >> 5;
    const int bh   = blockIdx.y;
    const int b = bh >> 4, h = bh & 15;
    const int qblk = gridDim.x - 1 - blockIdx.x;   // heavy first
    const int q0   = qblk * 64;

    const int qr = lane >> 2;
    const int c4 = lane & 3;
    const int ar = lane & 15;                      // A-frag ldsm row
    const int ac = (lane >> 4) * 4;                // A-frag ldsm col
    const int br = ((lane >> 4) << 3) + (lane & 7);// B-frag ldsm row
    const int bc = ((lane >> 3) & 1) * 4;          // B-frag ldsm col

    const uint32_t sQ = (uint32_t)__cvta_generic_to_shared(Qs);
    const uint32_t sK = (uint32_t)__cvta_generic_to_shared(Ks);
    const uint32_t sP = (uint32_t)__cvta_generic_to_shared(Ps);
    const uint32_t* Vu = (const uint32_t*)Vs;
    uint32_t* Psu = (uint32_t*)Ps;

    // Load Q tile (scale 1/sqrt(64) = 0.125: exact on tf32 values)
    for (int idx = tid; idx < 64 * 16; idx += 128) {
        const int r = idx >> 4, dq = (idx & 15) * 4;
        float4 v = *(const float4*)(qkv + (size_t)(b * TLEN + q0 + r) * C3 + h * HS + dq);
        *(float4*)&Qs[r * ASW + dq] =
            make_float4(v.x * 0.125f, v.y * 0.125f, v.z * 0.125f, v.w * 0.125f);
    }

    float oacc[8][4];
    #pragma unroll
    for (int j = 0; j < 8; ++j)
        #pragma unroll
        for (int c = 0; c < 4; ++c) oacc[j][c] = 0.0f;
    float lA = 0.0f, lB = 0.0f;

    __syncthreads();

    for (int kt = 0; kt <= qblk; ++kt) {
        // K and V tiles: raw vectorized copies (already tf32)
        for (int idx = tid; idx < 64 * 16; idx += 128) {
            const int r = idx >> 4, dq = (idx & 15) * 4;
            const float* base = qkv + (size_t)(b * TLEN + kt * 64 + r) * C3 + h * HS;
            *(float4*)&Ks[r * ASW + dq] = *(const float4*)(base + NEMBD + dq);
            *(float4*)&Vs[r * ASW + dq] = *(const float4*)(base + 2 * NEMBD + dq);
        }
        __syncthreads();

        // S = Q K^T : warp rows w*16..w*16+15 x 64 keys (ldsm4 frags)
        float sacc[8][4];
        #pragma unroll
        for (int j = 0; j < 8; ++j)
            #pragma unroll
            for (int c = 0; c < 4; ++c) sacc[j][c] = 0.0f;

        #pragma unroll
        for (int ks = 0; ks < 8; ++ks) {
            const int k0 = ks * 8;
            uint32_t af[4], bf[8][2];
            ldsm4(af, sQ + (uint32_t)((w * 16 + ar) * ASW + k0 + ac) * 4u);
            #pragma unroll
            for (int jp = 0; jp < 4; ++jp) {
                uint32_t r[4];
                ldsm4(r, sK + (uint32_t)((jp * 16 + br) * ASW + k0 + bc) * 4u);
                bf[2 * jp][0] = r[0]; bf[2 * jp][1] = r[1];
                bf[2 * jp + 1][0] = r[2]; bf[2 * jp + 1][1] = r[3];
            }
            #pragma unroll
            for (int j = 0; j < 8; ++j)
                mma8(sacc[j], af, bf[j]);
        }

        // Fixed-shift softmax weights + P store (tf32)
        const bool domask = (kt == qblk);
        const int rl  = w * 16 + qr;
        const int rgA = q0 + rl, rgB = rgA + 8;
        #pragma unroll
        for (int j = 0; j < 8; ++j) {
            float p0 = __expf(sacc[j][0]);
            float p1 = __expf(sacc[j][1]);
            float p2 = __expf(sacc[j][2]);
            float p3 = __expf(sacc[j][3]);
            if (domask) {
                const int kg = kt * 64 + j * 8 + 2 * c4;
                if (kg     > rgA) p0 = EMASK;
                if (kg + 1 > rgA) p1 = EMASK;
                if (kg     > rgB) p2 = EMASK;
                if (kg + 1 > rgB) p3 = EMASK;
            }
            lA += p0 + p1;
            lB += p2 + p3;
            *(uint2*)&Psu[rl * ASW + j * 8 + 2 * c4] =
                make_uint2(f2tf32(p0), f2tf32(p1));
            *(uint2*)&Psu[(rl + 8) * ASW + j * 8 + 2 * c4] =
                make_uint2(f2tf32(p2), f2tf32(p3));
        }
        __syncwarp();   // P rows are warp-private; order STS before LDSM

        // O += P V : P A-frags via ldsm4; V B-frags scalar (row-major Vs)
        #pragma unroll
        for (int ks = 0; ks < 8; ++ks) {
            const int k0 = ks * 8;
            uint32_t af[4];
            ldsm4(af, sP + (uint32_t)((w * 16 + ar) * ASW + k0 + ac) * 4u);
            #pragma unroll
            for (int j = 0; j < 8; ++j) {
                uint32_t bf[2];
                bf[0] = Vu[(k0 + c4) * ASW + j * 8 + qr];
                bf[1] = Vu[(k0 + 4 + c4) * ASW + j * 8 + qr];
                mma8(oacc[j], af, bf);
            }
        }
        __syncthreads();   // protect Ks/Vs before next tile load
    }

    // Tail: strictly-future keys, uniform weight EMASK.
    // Suffix V sum computed here from per-tile partials (t > qblk).
    const int nmask = TLEN - 64 * (qblk + 1);
    for (int d = tid; d < HS; d += 128) {
        float s = 0.0f;
        for (int t = qblk + 1; t < NT64; ++t)
            s += g_vsuf[((size_t)bh * NT64 + t) * HS + d];
        Ks[d] = s;
    }
    __syncthreads();

    lA += __shfl_xor_sync(0xffffffffu, lA, 1);
    lA += __shfl_xor_sync(0xffffffffu, lA, 2);
    lB += __shfl_xor_sync(0xffffffffu, lB, 1);
    lB += __shfl_xor_sync(0xffffffffu, lB, 2);
    const float invA = 1.0f / (lA + (float)nmask * EMASK);
    const float invB = 1.0f / (lB + (float)nmask * EMASK);

    const int rowA = b * TLEN + q0 + w * 16 + qr;
    float* yA = y + (size_t)rowA * NEMBD + h * HS;
    float* yB = y + (size_t)(rowA + 8) * NEMBD + h * HS;
    #pragma unroll
    for (int j = 0; j < 8; ++j) {
        const int d0 = j * 8 + 2 * c4;
        const float v0 = Ks[d0], v1 = Ks[d0 + 1];
        // y is consumed by the proj MMA: emit tf32-rounded values
        *(uint2*)&yA[d0] = make_uint2(f2tf32((oacc[j][0] + EMASK * v0) * invA),
                                      f2tf32((oacc[j][1] + EMASK * v1) * invA));
        *(uint2*)&yB[d0] = make_uint2(f2tf32((oacc[j][2] + EMASK * v0) * invB),
                                      f2tf32((oacc[j][3] + EMASK * v1) * invB));
    }
}

// ---------------------------------------------------------------------------
extern "C" void kernel_launch(void* const* d_in, const int* in_sizes, int n_in,
                              void* d_out, int out_size)
{
    const float* x      = (const float*)d_in[0];
    const float* w_attn = (const float*)d_in[1];
    const float* w_proj = (const float*)d_in[2];
    float* out = (float*)d_out;

    float *qkv, *y, *xc, *wac, *wpc;
    cudaGetSymbolAddress((void**)&qkv, g_qkv);
    cudaGetSymbolAddress((void**)&y,   g_y);
    cudaGetSymbolAddress((void**)&xc,  g_xc);
    cudaGetSymbolAddress((void**)&wac, g_wac);
    cudaGetSymbolAddress((void**)&wpc, g_wpc);

    const int gemm_smem = 6 * GST * (int)sizeof(uint32_t);   // 61440 B
    const int attn_smem = 4 * 64 * ASW * (int)sizeof(float); // 69632 B
    cudaFuncSetAttribute(gemm_tf32, cudaFuncAttributeMaxDynamicSharedMemorySize, gemm_smem);
    cudaFuncSetAttribute(attn_mma,  cudaFuncAttributeMaxDynamicSharedMemorySize, attn_smem);

    // 0) pre-round inputs to tf32, single fused launch
    round_all<<<2048, 256>>>(x, w_attn, w_proj);

    // 1) QKV projection (output tf32-rounded for attention MMAs)
    gemm_tf32<<<dim3(C3 / 128, BT / 128), 256, gemm_smem>>>(
        xc, wac, qkv, BT, C3, NEMBD, 1);

    // 2) V per-tile partial sums (suffix folded into attention tail)
    vsuf_partial<<<dim3(NT64, NBH), 64>>>(qkv);

    // 3) Attention (causal part + closed-form masked tail)
    attn_mma<<<dim3(NT64, NBH), 128, attn_smem>>>(qkv, y);

    // 4) Output projection (final output: full fp32)
    gemm_tf32<<<dim3(NEMBD / 128, BT / 128), 256, gemm_smem>>>(
        y, wpc, out, BT, NEMBD, NEMBD, 0);
}